// round 15
// baseline (speedup 1.0000x reference)
#include <cuda_runtime.h>
#include <cuda_fp16.h>
#include <cstdint>

// Sparse block attention: B=1, H=16, S=8192, D=64, BS=64, NB=128
// Pattern per q-block i: {0} U [max(0,i-7), i]; causal inside diagonal block.
// R15 = R8 structure (4 warps x 2 m-tiles = 128 rows = 2 q-blocks/CTA; K/V
// fragment loads amortized over 2x rows; V-frags shared across mi) +
// immediate per-nj exp (S live = 4 regs) -> ~160 regs, 3 CTAs/SM, no spill.
#define HEADS  16
#define SEQ    8192
#define DIM    64
#define BSZ    64
#define NBLK   128
#define LOCALW 8
#define LDH    72   // half stride: 144B rows -> conflict-free ldmatrix

__device__ __forceinline__ float ex2f(float x) {
    float y; asm("ex2.approx.ftz.f32 %0, %1;" : "=f"(y) : "f"(x)); return y;
}
__device__ __forceinline__ uint32_t pkh2(float a, float b) {
    __half2 h = __floats2half2_rn(a, b);
    return *reinterpret_cast<uint32_t*>(&h);
}
__device__ __forceinline__ void ldsm_x4(uint32_t& r0, uint32_t& r1, uint32_t& r2, uint32_t& r3, uint32_t a) {
    asm volatile("ldmatrix.sync.aligned.m8n8.x4.shared.b16 {%0,%1,%2,%3}, [%4];"
                 : "=r"(r0), "=r"(r1), "=r"(r2), "=r"(r3) : "r"(a));
}
__device__ __forceinline__ void ldsm_x4t(uint32_t& r0, uint32_t& r1, uint32_t& r2, uint32_t& r3, uint32_t a) {
    asm volatile("ldmatrix.sync.aligned.m8n8.x4.trans.shared.b16 {%0,%1,%2,%3}, [%4];"
                 : "=r"(r0), "=r"(r1), "=r"(r2), "=r"(r3) : "r"(a));
}
__device__ __forceinline__ void mma16816(float* c, uint32_t a0, uint32_t a1, uint32_t a2, uint32_t a3,
                                         uint32_t b0, uint32_t b1) {
    asm volatile("mma.sync.aligned.m16n8k16.row.col.f32.f16.f16.f32 "
                 "{%0,%1,%2,%3}, {%4,%5,%6,%7}, {%8,%9}, {%0,%1,%2,%3};"
                 : "+f"(c[0]), "+f"(c[1]), "+f"(c[2]), "+f"(c[3])
                 : "r"(a0), "r"(a1), "r"(a2), "r"(a3), "r"(b0), "r"(b1));
}

__global__ __launch_bounds__(128, 3)
void sparse_attn_hmma12(const float* __restrict__ q,
                        const float* __restrict__ k,
                        const float* __restrict__ v,
                        float* __restrict__ out)
{
    __shared__ __align__(16) __half Qs[128 * LDH];   // 18432 B
    __shared__ __align__(16) __half Ks[BSZ * LDH];   //  9216 B
    __shared__ __align__(16) __half Vs[BSZ * LDH];   //  9216 B

    const int bx   = blockIdx.x;          // 128-row q group (2 q-blocks)
    const int h    = blockIdx.y;
    const int tid  = threadIdx.x;
    const int lane = tid & 31;
    const int w    = tid >> 5;            // warp 0..3 -> rows 32w..32w+31

    const int my_ib = 2 * bx + (w >> 1);  // q-block this warp belongs to
    const int ibp   = 2 * bx + 1;
    const int nnz   = (ibp <= 8) ? (ibp + 1) : 10;

    const float qscale = 0.125f * 1.4426950408889634f;

    // ---- load + prescale 128-row Q tile ----
    {
        const float* qg = q + ((size_t)h * SEQ + (size_t)bx * 128) * DIM;
        #pragma unroll
        for (int j = 0; j < 16; ++j) {
            int i   = tid + 128 * j;
            int row = i >> 4;
            int c4  = (i & 15) << 2;
            float4 val = *(const float4*)(qg + row * DIM + c4);
            uint2 u;
            u.x = pkh2(val.x * qscale, val.y * qscale);
            u.y = pkh2(val.z * qscale, val.w * qscale);
            *(uint2*)&Qs[row * LDH + c4] = u;
        }
    }
    __syncthreads();

    const uint32_t qsb = (uint32_t)__cvta_generic_to_shared(Qs);
    const uint32_t ksb = (uint32_t)__cvta_generic_to_shared(Ks);
    const uint32_t vsb = (uint32_t)__cvta_generic_to_shared(Vs);

    // ---- persistent Q A-fragments: rows 32w + 16mi ----
    uint32_t aq[2][4][4];
    {
        int r   = lane & 15;
        int chi = (lane >> 4) * 8;
        #pragma unroll
        for (int mi = 0; mi < 2; ++mi) {
            uint32_t base = qsb + (((32 * w + 16 * mi + r) * LDH + chi) << 1);
            #pragma unroll
            for (int c = 0; c < 4; ++c)
                ldsm_x4(aq[mi][c][0], aq[mi][c][1], aq[mi][c][2], aq[mi][c][3],
                        base + ((16 * c) << 1));
        }
    }

    const int g8 = lane >> 3;
    const int r8 = lane & 7;

    float O[2][8][4];
    float lsum[2][2];
    #pragma unroll
    for (int mi = 0; mi < 2; ++mi) {
        lsum[mi][0] = 0.f; lsum[mi][1] = 0.f;
        #pragma unroll
        for (int j = 0; j < 8; ++j)
            #pragma unroll
            for (int e = 0; e < 4; ++e) O[mi][j][e] = 0.f;
    }

    const int rbase0 = 32 * (w & 1);      // block-local row base of this warp
    const int c0loc  = 2 * (lane & 3);
    const int rq     = lane >> 2;

    for (int t = 0; t < nnz; ++t) {
        const int jb = (ibp <= 8) ? t : ((t == 0) ? 0 : (ibp - 9 + t));
        const bool active = (jb == 0) || (jb >= my_ib - (LOCALW - 1) && jb <= my_ib);

        // ---- load K, V tiles -> fp16 smem ----
        const float* kg = k + ((size_t)h * SEQ + (size_t)jb * BSZ) * DIM;
        const float* vg = v + ((size_t)h * SEQ + (size_t)jb * BSZ) * DIM;
        #pragma unroll
        for (int j = 0; j < 8; ++j) {
            int i   = tid + 128 * j;
            int row = i >> 4;
            int c4  = (i & 15) << 2;
            float4 kv = *(const float4*)(kg + row * DIM + c4);
            uint2 uk;
            uk.x = pkh2(kv.x, kv.y);
            uk.y = pkh2(kv.z, kv.w);
            *(uint2*)&Ks[row * LDH + c4] = uk;
            float4 vv = *(const float4*)(vg + row * DIM + c4);
            uint2 uv;
            uv.x = pkh2(vv.x, vv.y);
            uv.y = pkh2(vv.z, vv.w);
            *(uint2*)&Vs[row * LDH + c4] = uv;
        }
        __syncthreads();

        if (active) {
            const bool diag = (jb == my_ib);
            uint32_t pa[2][4][4];

            // ---- per m-tile: S MMA per nj with immediate exp (S live = 4) ----
            #pragma unroll
            for (int mi = 0; mi < 2; ++mi) {
                #pragma unroll
                for (int nj = 0; nj < 8; ++nj) {
                    float S[4] = {0.f, 0.f, 0.f, 0.f};
                    uint32_t a0 = ksb + (((8 * nj + r8) * LDH + 8 * (g8 & 1) + 16 * (g8 >> 1)) << 1);
                    uint32_t b0, b1, b2, b3, b4, b5, b6, b7;
                    ldsm_x4(b0, b1, b2, b3, a0);
                    ldsm_x4(b4, b5, b6, b7, a0 + 64);
                    mma16816(S, aq[mi][0][0], aq[mi][0][1], aq[mi][0][2], aq[mi][0][3], b0, b1);
                    mma16816(S, aq[mi][1][0], aq[mi][1][1], aq[mi][1][2], aq[mi][1][3], b2, b3);
                    mma16816(S, aq[mi][2][0], aq[mi][2][1], aq[mi][2][2], aq[mi][2][3], b4, b5);
                    mma16816(S, aq[mi][3][0], aq[mi][3][1], aq[mi][3][2], aq[mi][3][3], b6, b7);

                    if (diag) {
                        int r0 = rbase0 + 16 * mi + rq;
                        int cn = 8 * nj + c0loc;
                        if (cn     > r0)     S[0] = -1e30f;
                        if (cn + 1 > r0)     S[1] = -1e30f;
                        if (cn     > r0 + 8) S[2] = -1e30f;
                        if (cn + 1 > r0 + 8) S[3] = -1e30f;
                    }

                    float p0 = ex2f(S[0]);
                    float p1 = ex2f(S[1]);
                    float p2 = ex2f(S[2]);
                    float p3 = ex2f(S[3]);
                    lsum[mi][0] += p0 + p1;
                    lsum[mi][1] += p2 + p3;
                    int c  = nj >> 1;
                    int hi = (nj & 1) << 1;
                    pa[mi][c][hi]     = pkh2(p0, p1);
                    pa[mi][c][hi + 1] = pkh2(p2, p3);
                }
            }

            // ---- O += P @ V : V frags loaded once per nj, shared across mi ----
            #pragma unroll
            for (int nj = 0; nj < 8; ++nj) {
                uint32_t v0 = vsb + (((8 * g8 + r8) * LDH + 8 * nj) << 1);
                uint32_t v1 = vsb + (((32 + 8 * g8 + r8) * LDH + 8 * nj) << 1);
                uint32_t c0, c1, c2, c3, c4, c5, c6, c7;
                ldsm_x4t(c0, c1, c2, c3, v0);
                ldsm_x4t(c4, c5, c6, c7, v1);
                #pragma unroll
                for (int mi = 0; mi < 2; ++mi) {
                    mma16816(O[mi][nj], pa[mi][0][0], pa[mi][0][1], pa[mi][0][2], pa[mi][0][3], c0, c1);
                    mma16816(O[mi][nj], pa[mi][1][0], pa[mi][1][1], pa[mi][1][2], pa[mi][1][3], c2, c3);
                    mma16816(O[mi][nj], pa[mi][2][0], pa[mi][2][1], pa[mi][2][2], pa[mi][2][3], c4, c5);
                    mma16816(O[mi][nj], pa[mi][3][0], pa[mi][3][1], pa[mi][3][2], pa[mi][3][3], c6, c7);
                }
            }
        }
        __syncthreads();
    }

    // ---- epilogue: normalize + store ----
    float* og = out + ((size_t)h * SEQ + (size_t)bx * 128) * DIM;
    #pragma unroll
    for (int mi = 0; mi < 2; ++mi) {
        float s0 = lsum[mi][0] + __shfl_xor_sync(0xffffffffu, lsum[mi][0], 1);
        s0 += __shfl_xor_sync(0xffffffffu, s0, 2);
        float s1 = lsum[mi][1] + __shfl_xor_sync(0xffffffffu, lsum[mi][1], 1);
        s1 += __shfl_xor_sync(0xffffffffu, s1, 2);
        float inv0 = 1.0f / s0;
        float inv1 = 1.0f / s1;
        int gr = 32 * w + 16 * mi + rq;     // row within 128-row group
        #pragma unroll
        for (int nj = 0; nj < 8; ++nj) {
            int cn = 8 * nj + c0loc;
            float2 o0 = make_float2(O[mi][nj][0] * inv0, O[mi][nj][1] * inv0);
            float2 o1 = make_float2(O[mi][nj][2] * inv1, O[mi][nj][3] * inv1);
            *(float2*)(og + (size_t)gr * DIM + cn)       = o0;
            *(float2*)(og + (size_t)(gr + 8) * DIM + cn) = o1;
        }
    }
}

extern "C" void kernel_launch(void* const* d_in, const int* in_sizes, int n_in,
                              void* d_out, int out_size)
{
    const float* q = (const float*)d_in[0];
    const float* k = (const float*)d_in[1];
    const float* v = (const float*)d_in[2];
    float* out = (float*)d_out;

    dim3 grid(NBLK / 2, HEADS);
    sparse_attn_hmma12<<<grid, 128>>>(q, k, v, out);
}

// round 16
// speedup vs baseline: 1.1628x; 1.1628x over previous
#include <cuda_runtime.h>
#include <cuda_fp16.h>
#include <cstdint>

// Sparse block attention: B=1, H=16, S=8192, D=64, BS=64, NB=128
// Pattern per q-block i: {0} U [max(0,i-7), i]; causal inside diagonal block.
// R16: two kernels. (1) preconvert K,V -> fp16 device scratch once.
// (2) R8-structure main (2 q-blocks/CTA, 4 warps x 2 m-tiles, fixed-max,
//     bulk-S per mi, V-frags shared) with cp.async.cg fp16 K/V double buffer.
#define HEADS  16
#define SEQ    8192
#define DIM    64
#define BSZ    64
#define NBLK   128
#define LOCALW 8
#define LDH    72   // half stride: 144B rows -> conflict-free ldmatrix

// fp16 copies of K and V: [h][s][d], 16.8 MB each
__device__ __align__(16) __half KF[HEADS * SEQ * DIM];
__device__ __align__(16) __half VF[HEADS * SEQ * DIM];

// dynamic smem byte offsets
#define QS_OFF  0         // 128 rows x 144B = 18432
#define K0_OFF  18432     // 2 x 9216
#define V0_OFF  36864     // 2 x 9216
#define SMEM_TOTAL 55296
#define TILE_B  9216

__device__ __forceinline__ float ex2f(float x) {
    float y; asm("ex2.approx.ftz.f32 %0, %1;" : "=f"(y) : "f"(x)); return y;
}
__device__ __forceinline__ uint32_t pkh2(float a, float b) {
    __half2 h = __floats2half2_rn(a, b);
    return *reinterpret_cast<uint32_t*>(&h);
}
__device__ __forceinline__ void cpa16(uint32_t dst, const void* src) {
    asm volatile("cp.async.cg.shared.global [%0], [%1], 16;" :: "r"(dst), "l"(src));
}
__device__ __forceinline__ void ldsm_x4(uint32_t& r0, uint32_t& r1, uint32_t& r2, uint32_t& r3, uint32_t a) {
    asm volatile("ldmatrix.sync.aligned.m8n8.x4.shared.b16 {%0,%1,%2,%3}, [%4];"
                 : "=r"(r0), "=r"(r1), "=r"(r2), "=r"(r3) : "r"(a));
}
__device__ __forceinline__ void ldsm_x4t(uint32_t& r0, uint32_t& r1, uint32_t& r2, uint32_t& r3, uint32_t a) {
    asm volatile("ldmatrix.sync.aligned.m8n8.x4.trans.shared.b16 {%0,%1,%2,%3}, [%4];"
                 : "=r"(r0), "=r"(r1), "=r"(r2), "=r"(r3) : "r"(a));
}
__device__ __forceinline__ void mma16816(float* c, uint32_t a0, uint32_t a1, uint32_t a2, uint32_t a3,
                                         uint32_t b0, uint32_t b1) {
    asm volatile("mma.sync.aligned.m16n8k16.row.col.f32.f16.f16.f32 "
                 "{%0,%1,%2,%3}, {%4,%5,%6,%7}, {%8,%9}, {%0,%1,%2,%3};"
                 : "+f"(c[0]), "+f"(c[1]), "+f"(c[2]), "+f"(c[3])
                 : "r"(a0), "r"(a1), "r"(a2), "r"(a3), "r"(b0), "r"(b1));
}

// ---------------- kernel 1: K/V f32 -> f16 scratch ----------------
__global__ __launch_bounds__(256)
void preconvert_kv(const float* __restrict__ k, const float* __restrict__ v)
{
    int idx = blockIdx.x * 256 + threadIdx.x;           // float4 index
    const float4* k4 = (const float4*)k;
    const float4* v4 = (const float4*)v;
    float4 a = k4[idx];
    float4 b = v4[idx];
    uint2 ua, ub;
    ua.x = pkh2(a.x, a.y); ua.y = pkh2(a.z, a.w);
    ub.x = pkh2(b.x, b.y); ub.y = pkh2(b.z, b.w);
    ((uint2*)KF)[idx] = ua;
    ((uint2*)VF)[idx] = ub;
}

// ---------------- kernel 2: main attention ----------------
__global__ __launch_bounds__(128, 2)
void sparse_attn_hmma13(const float* __restrict__ q,
                        float* __restrict__ out)
{
    extern __shared__ __align__(16) char dsm[];
    __half* Qs = (__half*)(dsm + QS_OFF);

    const int bx   = blockIdx.x;          // 128-row q group (2 q-blocks)
    const int h    = blockIdx.y;
    const int tid  = threadIdx.x;
    const int lane = tid & 31;
    const int w    = tid >> 5;            // warp 0..3 -> rows 32w..32w+31

    const int my_ib = 2 * bx + (w >> 1);
    const int ibp   = 2 * bx + 1;
    const int nnz   = (ibp <= 8) ? (ibp + 1) : 10;

    const uint32_t smb = (uint32_t)__cvta_generic_to_shared(dsm);

    // cp.async coords: 4 chunks of 16B per tensor per thread; chunk c = tid+128j
    const int crow = tid >> 3;            // +16 per j  (c>>3 = tid>>3 + 16j)
    const int coff = (tid & 7) * 16;      // byte offset within 128B row

    const __half* khf = KF + (size_t)h * SEQ * DIM;
    const __half* vhf = VF + (size_t)h * SEQ * DIM;

    // ---- prologue: issue tile 0 (jb=0), then load+convert Q ----
    {
        #pragma unroll
        for (int j = 0; j < 4; ++j) {
            int row = crow + 16 * j;
            cpa16(smb + K0_OFF + row * 144 + coff, (const char*)(khf + row * DIM) + coff);
            cpa16(smb + V0_OFF + row * 144 + coff, (const char*)(vhf + row * DIM) + coff);
        }
        asm volatile("cp.async.commit_group;");
    }
    {
        const float qscale = 0.125f * 1.4426950408889634f;
        const float* qg = q + ((size_t)h * SEQ + (size_t)bx * 128) * DIM;
        #pragma unroll
        for (int j = 0; j < 16; ++j) {
            int i   = tid + 128 * j;
            int row = i >> 4;
            int c4  = (i & 15) << 2;
            float4 val = *(const float4*)(qg + row * DIM + c4);
            uint2 u;
            u.x = pkh2(val.x * qscale, val.y * qscale);
            u.y = pkh2(val.z * qscale, val.w * qscale);
            *(uint2*)&Qs[row * LDH + c4] = u;
        }
    }
    __syncthreads();

    // ---- persistent Q A-fragments ----
    uint32_t aq[2][4][4];
    {
        int r   = lane & 15;
        int chi = (lane >> 4) * 8;
        #pragma unroll
        for (int mi = 0; mi < 2; ++mi) {
            uint32_t base = smb + QS_OFF + ((32 * w + 16 * mi + r) * LDH + chi) * 2;
            #pragma unroll
            for (int c = 0; c < 4; ++c)
                ldsm_x4(aq[mi][c][0], aq[mi][c][1], aq[mi][c][2], aq[mi][c][3],
                        base + ((16 * c) << 1));
        }
    }

    const int g8 = lane >> 3;
    const int r8 = lane & 7;

    float O[2][8][4];
    float lsum[2][2];
    #pragma unroll
    for (int mi = 0; mi < 2; ++mi) {
        lsum[mi][0] = 0.f; lsum[mi][1] = 0.f;
        #pragma unroll
        for (int j = 0; j < 8; ++j)
            #pragma unroll
            for (int e = 0; e < 4; ++e) O[mi][j][e] = 0.f;
    }

    const int rbase0 = 32 * (w & 1);
    const int c0loc  = 2 * (lane & 3);
    const int rq     = lane >> 2;

    for (int t = 0; t < nnz; ++t) {
        const int  buf = t & 1;
        const bool pf  = (t + 1 < nnz);
        const int  jb  = (ibp <= 8) ? t : ((t == 0) ? 0 : (ibp - 9 + t));

        // ---- issue cp.async for tile t+1 into other buffer ----
        if (pf) {
            const int jn = (ibp <= 8) ? (t + 1) : (ibp - 8 + t);
            const __half* kg = khf + (size_t)jn * BSZ * DIM;
            const __half* vg = vhf + (size_t)jn * BSZ * DIM;
            const uint32_t kd = smb + K0_OFF + (buf ^ 1) * TILE_B;
            const uint32_t vd = smb + V0_OFF + (buf ^ 1) * TILE_B;
            #pragma unroll
            for (int j = 0; j < 4; ++j) {
                int row = crow + 16 * j;
                cpa16(kd + row * 144 + coff, (const char*)(kg + row * DIM) + coff);
                cpa16(vd + row * 144 + coff, (const char*)(vg + row * DIM) + coff);
            }
            asm volatile("cp.async.commit_group;");
            asm volatile("cp.async.wait_group 1;");   // tile t landed
        } else {
            asm volatile("cp.async.wait_group 0;");
        }
        __syncthreads();

        const uint32_t kb = smb + K0_OFF + buf * TILE_B;
        const uint32_t vb = smb + V0_OFF + buf * TILE_B;

        const bool active = (jb == 0) || (jb >= my_ib - (LOCALW - 1) && jb <= my_ib);
        if (active) {
            const bool diag = (jb == my_ib);
            uint32_t pa[2][4][4];

            // ---- per m-tile: bulk S MMA, mask, bulk exp, pack (R8 order) ----
            #pragma unroll
            for (int mi = 0; mi < 2; ++mi) {
                float S[8][4];
                #pragma unroll
                for (int j = 0; j < 8; ++j)
                    #pragma unroll
                    for (int e = 0; e < 4; ++e) S[j][e] = 0.f;

                #pragma unroll
                for (int nj = 0; nj < 8; ++nj) {
                    uint32_t a0 = kb + ((8 * nj + r8) * LDH + 8 * (g8 & 1) + 16 * (g8 >> 1)) * 2;
                    uint32_t b0, b1, b2, b3, b4, b5, b6, b7;
                    ldsm_x4(b0, b1, b2, b3, a0);
                    ldsm_x4(b4, b5, b6, b7, a0 + 64);
                    mma16816(S[nj], aq[mi][0][0], aq[mi][0][1], aq[mi][0][2], aq[mi][0][3], b0, b1);
                    mma16816(S[nj], aq[mi][1][0], aq[mi][1][1], aq[mi][1][2], aq[mi][1][3], b2, b3);
                    mma16816(S[nj], aq[mi][2][0], aq[mi][2][1], aq[mi][2][2], aq[mi][2][3], b4, b5);
                    mma16816(S[nj], aq[mi][3][0], aq[mi][3][1], aq[mi][3][2], aq[mi][3][3], b6, b7);
                }

                if (diag) {
                    int r0 = rbase0 + 16 * mi + rq;
                    #pragma unroll
                    for (int nj = 0; nj < 8; ++nj) {
                        int cn = 8 * nj + c0loc;
                        if (cn     > r0)     S[nj][0] = -1e30f;
                        if (cn + 1 > r0)     S[nj][1] = -1e30f;
                        if (cn     > r0 + 8) S[nj][2] = -1e30f;
                        if (cn + 1 > r0 + 8) S[nj][3] = -1e30f;
                    }
                }

                float ps0 = 0.f, ps1 = 0.f;
                #pragma unroll
                for (int nj = 0; nj < 8; ++nj) {
                    S[nj][0] = ex2f(S[nj][0]);
                    S[nj][1] = ex2f(S[nj][1]);
                    S[nj][2] = ex2f(S[nj][2]);
                    S[nj][3] = ex2f(S[nj][3]);
                    ps0 += S[nj][0] + S[nj][1];
                    ps1 += S[nj][2] + S[nj][3];
                }
                lsum[mi][0] += ps0;
                lsum[mi][1] += ps1;

                #pragma unroll
                for (int c = 0; c < 4; ++c) {
                    pa[mi][c][0] = pkh2(S[2 * c][0],     S[2 * c][1]);
                    pa[mi][c][1] = pkh2(S[2 * c][2],     S[2 * c][3]);
                    pa[mi][c][2] = pkh2(S[2 * c + 1][0], S[2 * c + 1][1]);
                    pa[mi][c][3] = pkh2(S[2 * c + 1][2], S[2 * c + 1][3]);
                }
            }

            // ---- O += P @ V : V frags loaded once per nj, shared across mi ----
            #pragma unroll
            for (int nj = 0; nj < 8; ++nj) {
                uint32_t v0 = vb + ((8 * g8 + r8) * LDH + 8 * nj) * 2;
                uint32_t v1 = vb + ((32 + 8 * g8 + r8) * LDH + 8 * nj) * 2;
                uint32_t c0, c1, c2, c3, c4, c5, c6, c7;
                ldsm_x4t(c0, c1, c2, c3, v0);
                ldsm_x4t(c4, c5, c6, c7, v1);
                #pragma unroll
                for (int mi = 0; mi < 2; ++mi) {
                    mma16816(O[mi][nj], pa[mi][0][0], pa[mi][0][1], pa[mi][0][2], pa[mi][0][3], c0, c1);
                    mma16816(O[mi][nj], pa[mi][1][0], pa[mi][1][1], pa[mi][1][2], pa[mi][1][3], c2, c3);
                    mma16816(O[mi][nj], pa[mi][2][0], pa[mi][2][1], pa[mi][2][2], pa[mi][2][3], c4, c5);
                    mma16816(O[mi][nj], pa[mi][3][0], pa[mi][3][1], pa[mi][3][2], pa[mi][3][3], c6, c7);
                }
            }
        }
        __syncthreads();   // readers done before next iter's cp.async overwrites
    }

    // ---- epilogue: normalize + store ----
    float* og = out + ((size_t)h * SEQ + (size_t)bx * 128) * DIM;
    #pragma unroll
    for (int mi = 0; mi < 2; ++mi) {
        float s0 = lsum[mi][0] + __shfl_xor_sync(0xffffffffu, lsum[mi][0], 1);
        s0 += __shfl_xor_sync(0xffffffffu, s0, 2);
        float s1 = lsum[mi][1] + __shfl_xor_sync(0xffffffffu, lsum[mi][1], 1);
        s1 += __shfl_xor_sync(0xffffffffu, s1, 2);
        float inv0 = 1.0f / s0;
        float inv1 = 1.0f / s1;
        int gr = 32 * w + 16 * mi + rq;
        #pragma unroll
        for (int nj = 0; nj < 8; ++nj) {
            int cn = 8 * nj + c0loc;
            float2 o0 = make_float2(O[mi][nj][0] * inv0, O[mi][nj][1] * inv0);
            float2 o1 = make_float2(O[mi][nj][2] * inv1, O[mi][nj][3] * inv1);
            *(float2*)(og + (size_t)gr * DIM + cn)       = o0;
            *(float2*)(og + (size_t)(gr + 8) * DIM + cn) = o1;
        }
    }
}

extern "C" void kernel_launch(void* const* d_in, const int* in_sizes, int n_in,
                              void* d_out, int out_size)
{
    const float* q = (const float*)d_in[0];
    const float* k = (const float*)d_in[1];
    const float* v = (const float*)d_in[2];
    float* out = (float*)d_out;

    // kernel 1: K/V -> fp16 scratch (HEADS*SEQ*DIM/4 float4s / 256 thr)
    preconvert_kv<<<HEADS * SEQ * DIM / 4 / 256, 256>>>(k, v);

    // kernel 2: attention
    cudaFuncSetAttribute(sparse_attn_hmma13,
                         cudaFuncAttributeMaxDynamicSharedMemorySize, SMEM_TOTAL);
    dim3 grid(NBLK / 2, HEADS);
    sparse_attn_hmma13<<<grid, 128, SMEM_TOTAL>>>(q, out);
}